// round 5
// baseline (speedup 1.0000x reference)
#include <cuda_runtime.h>

// LinearChainCRF: mean(logZ - gold) over B=16384 sequences of T=512, N_TAGS=4.
//
// Algebra: the reference's logsumexp is over the LAST axis (j); alpha[i] is
// constant in j, so the "scan" is purely additive:
//   alpha_T[i] = em[0,i] + sum_{t>=1} mask_t * log(s_i(t)),
//   s_i(t)     = sum_j exp(trans[i,j]) * exp(em[t,j])   (|e| <~ 6 -> no norm)
//   logZ       = logsumexp_i(alpha_T[i]);  result = mean(logZ - gold).
// Warp-per-sequence, 16 timesteps/thread stride-32. prev-tag via shfl (no 2nd
// tag load). Logs grouped 4-at-a-time via products (fp32-safe range).
// Final mean: deterministic Q32.32 fixed-point atomicAdd per block.

#define T_LEN 512
#define WARPS_PER_BLOCK 8
#define FIXED_SCALE 4294967296.0   // 2^32

__device__ unsigned long long g_accum;

__global__ void init_kernel() { g_accum = 0ULL; }

__global__ __launch_bounds__(32 * WARPS_PER_BLOCK)
void crf_warp_kernel(const float* __restrict__ emissions,
                     const void* __restrict__ tags_raw,
                     const void* __restrict__ mask_raw,
                     const float* __restrict__ transitions)
{
    __shared__ float trans_s[16];
    __shared__ float expT_s[16];
    __shared__ float warp_res[WARPS_PER_BLOCK];

    const int lane = threadIdx.x & 31;
    const int warp = threadIdx.x >> 5;
    const int b = blockIdx.x * WARPS_PER_BLOCK + warp;
    const unsigned full = 0xffffffffu;

    if (threadIdx.x < 16) {
        float tv = transitions[threadIdx.x];
        trans_s[threadIdx.x] = tv;
        expT_s[threadIdx.x] = __expf(tv);
    }
    __syncthreads();

    // ---- warp-parallel dtype probes (first words; L2-resident after block 0) --
    const int* tags32p = (const int*)tags_raw;
    const unsigned int* mask32p = (const unsigned int*)mask_raw;
    // tags int64 <=> odd int32 words all zero (tags in [0,4); P(miss)~(1/4)^32)
    const int tag_is64 = (__ballot_sync(full, tags32p[2 * lane + 1] != 0) == 0u);
    // mask: u8 -> words 0x01010101 (hi bytes set); i32 -> odd words nonzero; i64 -> neither
    const unsigned int hi = __ballot_sync(full, (mask32p[lane] & 0xFFFFFF00u) != 0u);
    const unsigned int od = __ballot_sync(full, mask32p[2 * lane + 1] != 0u);
    const int mask_w = hi ? 1 : (od ? 4 : 8);

    float eT[16];
    #pragma unroll
    for (int i = 0; i < 16; ++i) eT[i] = expT_s[i];

    const long long base = (long long)b * T_LEN;
    const float4* em4 = (const float4*)emissions;
    const long long* tg64 = (const long long*)tags_raw;
    const int* tg32 = (const int*)tags_raw;

    float c0 = 0.f, c1 = 0.f, c2 = 0.f, c3 = 0.f, gold = 0.f;
    float a0 = 0.f, a1 = 0.f, a2 = 0.f, a3 = 0.f;   // alpha0 (lane 0 only)
    int carry = 0;                                   // tag at t = 32*i - 1

    #pragma unroll
    for (int chunk = 0; chunk < 4; ++chunk) {
        float pr0 = 1.f, pr1 = 1.f, pr2 = 1.f, pr3 = 1.f;
        #pragma unroll
        for (int u = 0; u < 4; ++u) {
            const int i = chunk * 4 + u;
            const int t = i * 32 + lane;
            const long long idx = base + t;

            const float4 e = __ldcs(&em4[idx]);
            const int tag = tag_is64 ? (int)__ldcs(&tg64[idx]) : __ldcs(&tg32[idx]);

            int ptag = __shfl_up_sync(full, tag, 1);
            if (lane == 0) ptag = carry;
            carry = __shfl_sync(full, tag, 31);

            float m;
            if (mask_w == 1)      m = ((const unsigned char*)mask_raw)[idx] ? 1.0f : 0.0f;
            else if (mask_w == 4) m = __ldcs(&((const int*)mask_raw)[idx]) ? 1.0f : 0.0f;
            else                  m = __ldcs(&((const long long*)mask_raw)[idx]) ? 1.0f : 0.0f;

            const float etag = (tag == 0) ? e.x : (tag == 1) ? e.y : (tag == 2) ? e.z : e.w;

            if (i == 0 && lane == 0) {
                gold += m * etag;
                a0 = e.x; a1 = e.y; a2 = e.z; a3 = e.w;
            } else {
                gold += m * (etag + trans_s[ptag * 4 + tag]);
                const float q0 = __expf(e.x);
                const float q1 = __expf(e.y);
                const float q2 = __expf(e.z);
                const float q3 = __expf(e.w);
                float s0 = eT[0]  * q0 + eT[1]  * q1 + eT[2]  * q2 + eT[3]  * q3;
                float s1 = eT[4]  * q0 + eT[5]  * q1 + eT[6]  * q2 + eT[7]  * q3;
                float s2 = eT[8]  * q0 + eT[9]  * q1 + eT[10] * q2 + eT[11] * q3;
                float s3 = eT[12] * q0 + eT[13] * q1 + eT[14] * q2 + eT[15] * q3;
                pr0 *= (m != 0.f) ? s0 : 1.0f;
                pr1 *= (m != 0.f) ? s1 : 1.0f;
                pr2 *= (m != 0.f) ? s2 : 1.0f;
                pr3 *= (m != 0.f) ? s3 : 1.0f;
            }
        }
        c0 += __logf(pr0);
        c1 += __logf(pr1);
        c2 += __logf(pr2);
        c3 += __logf(pr3);
    }

    // warp-wide sums of {c0,c1,c2,c3,gold}
    float v[5] = {c0, c1, c2, c3, gold};
    #pragma unroll
    for (int k = 0; k < 5; ++k) {
        float x = v[k];
        x += __shfl_xor_sync(full, x, 16);
        x += __shfl_xor_sync(full, x, 8);
        x += __shfl_xor_sync(full, x, 4);
        x += __shfl_xor_sync(full, x, 2);
        x += __shfl_xor_sync(full, x, 1);
        v[k] = x;
    }

    if (lane == 0) {
        const float f0 = a0 + v[0];
        const float f1 = a1 + v[1];
        const float f2 = a2 + v[2];
        const float f3 = a3 + v[3];
        const float mx = fmaxf(fmaxf(f0, f1), fmaxf(f2, f3));
        const float logZ = mx + __logf(__expf(f0 - mx) + __expf(f1 - mx) +
                                       __expf(f2 - mx) + __expf(f3 - mx));
        warp_res[warp] = logZ - v[4];
    }
    __syncthreads();

    // Block fold -> one deterministic Q32.32 atomic per block.
    if (threadIdx.x == 0) {
        double s = 0.0;
        #pragma unroll
        for (int w = 0; w < WARPS_PER_BLOCK; ++w) s += (double)warp_res[w];
        long long q = llrint(s * FIXED_SCALE);
        atomicAdd(&g_accum, (unsigned long long)q);
    }
}

__global__ void finalize_kernel(float* __restrict__ out, int B)
{
    long long q = (long long)g_accum;   // two's-complement round-trip is exact
    out[0] = (float)(((double)q / FIXED_SCALE) / (double)B);
}

extern "C" void kernel_launch(void* const* d_in, const int* in_sizes, int n_in,
                              void* d_out, int out_size)
{
    const float* emissions   = (const float*)d_in[0];
    const void*  tags        = (const void*)d_in[1];
    const void*  mask        = (const void*)d_in[2];
    const float* transitions = (const float*)d_in[3];

    const int B = in_sizes[0] / (T_LEN * 4);   // emissions: B*T*4 floats

    init_kernel<<<1, 1>>>();
    crf_warp_kernel<<<B / WARPS_PER_BLOCK, 32 * WARPS_PER_BLOCK>>>(
        emissions, tags, mask, transitions);
    finalize_kernel<<<1, 1>>>((float*)d_out, B);
}

// round 7
// speedup vs baseline: 1.0622x; 1.0622x over previous
#include <cuda_runtime.h>

// LinearChainCRF: mean(logZ - gold) over B=16384 sequences of T=512, N_TAGS=4.
//
// Algebra: the reference's logsumexp is over the LAST axis (j); alpha[i] is
// constant in j, so the "scan" is purely additive:
//   alpha_T[i] = em[0,i] + sum_{t>=1} mask_t * log(s_i(t)),
//   s_i(t)     = sum_j exp(trans[i,j]) * exp(em[t,j])   (|e| <~ 6 -> no norm)
//   logZ       = logsumexp_i(alpha_T[i]);  result = mean(logZ - gold).
//
// Warp-per-sequence, 16 timesteps/thread stride-32 (all loads independent ->
// full MLP; prev-tag is a second load, L1-hit). Logs grouped 4-at-a-time via
// products (fp32-safe range). Single kernel: last block (threadfence-reduction
// ticket) sums the 16384 partials in fixed order -> deterministic.
// 30KB static smem pad caps occupancy at 7 blocks/SM: grid 2048 / (148*7=1036)
// = 2 waves at 98.8% fill instead of 8/SM's 2 waves at 86%.

#define T_LEN 512
#define MAX_B 16384
#define WARPS_PER_BLOCK 8
#define NTHREADS (32 * WARPS_PER_BLOCK)
#define SMEM_PAD_BYTES 30720

__device__ float g_partial[MAX_B];
__device__ unsigned int g_ticket;   // zero-init at load; used modulo grid size

__global__ __launch_bounds__(NTHREADS)
void crf_warp_kernel(const float* __restrict__ emissions,
                     const void* __restrict__ tags_raw,
                     const void* __restrict__ mask_raw,
                     const float* __restrict__ transitions,
                     float* __restrict__ out, int B)
{
    // Occupancy pad (7 blocks/SM); live tables are aliased into it.
    __shared__ __align__(16) char smem_pad[SMEM_PAD_BYTES];
    float* trans_s = (float*)smem_pad;             // [16]
    float* expT_s  = trans_s + 16;                 // [16]
    double* shred  = (double*)(smem_pad + 256);    // [NTHREADS] for final reduce
    __shared__ int s_is_last;

    const int lane = threadIdx.x & 31;
    const int warp = threadIdx.x >> 5;
    const int b = blockIdx.x * WARPS_PER_BLOCK + warp;
    const unsigned full = 0xffffffffu;

    if (threadIdx.x < 16) {
        float tv = transitions[threadIdx.x];
        trans_s[threadIdx.x] = tv;
        expT_s[threadIdx.x] = __expf(tv);
    }
    __syncthreads();

    // ---- warp-parallel dtype probes (first words; L2-resident after block 0) --
    const int* tags32p = (const int*)tags_raw;
    const unsigned int* mask32p = (const unsigned int*)mask_raw;
    // tags int64 <=> odd int32 words all zero (tags in [0,4); P(miss)~(1/4)^32)
    const int tag_is64 = (__ballot_sync(full, tags32p[2 * lane + 1] != 0) == 0u);
    // mask: u8 -> hi bytes of words set; i32 -> odd words nonzero; i64 -> neither
    const unsigned int hi = __ballot_sync(full, (mask32p[lane] & 0xFFFFFF00u) != 0u);
    const unsigned int od = __ballot_sync(full, mask32p[2 * lane + 1] != 0u);
    const int mask_w = hi ? 1 : (od ? 4 : 8);

    float eT[16];
    #pragma unroll
    for (int i = 0; i < 16; ++i) eT[i] = expT_s[i];

    const long long base = (long long)b * T_LEN;
    const float4* em4 = (const float4*)emissions;
    const long long* tg64 = (const long long*)tags_raw;
    const int* tg32 = (const int*)tags_raw;

    float c0 = 0.f, c1 = 0.f, c2 = 0.f, c3 = 0.f, gold = 0.f;
    float a0 = 0.f, a1 = 0.f, a2 = 0.f, a3 = 0.f;   // alpha0 (lane 0 only)

    #pragma unroll
    for (int chunk = 0; chunk < 4; ++chunk) {
        float pr0 = 1.f, pr1 = 1.f, pr2 = 1.f, pr3 = 1.f;
        #pragma unroll
        for (int u = 0; u < 4; ++u) {
            const int t = (chunk * 4 + u) * 32 + lane;
            const long long idx = base + t;

            const float4 e = em4[idx];

            int tag, ptag = 0;
            if (tag_is64) {
                tag = (int)tg64[idx];
                if (t > 0) ptag = (int)tg64[idx - 1];
            } else {
                tag = tg32[idx];
                if (t > 0) ptag = tg32[idx - 1];
            }
            float m;
            if (mask_w == 1)      m = ((const unsigned char*)mask_raw)[idx] ? 1.0f : 0.0f;
            else if (mask_w == 4) m = ((const int*)mask_raw)[idx] ? 1.0f : 0.0f;
            else                  m = ((const long long*)mask_raw)[idx] ? 1.0f : 0.0f;

            const float etag = (tag == 0) ? e.x : (tag == 1) ? e.y : (tag == 2) ? e.z : e.w;

            if (t == 0) {
                gold += m * etag;
                a0 = e.x; a1 = e.y; a2 = e.z; a3 = e.w;
            } else {
                gold += m * (etag + trans_s[ptag * 4 + tag]);
                const float q0 = __expf(e.x);
                const float q1 = __expf(e.y);
                const float q2 = __expf(e.z);
                const float q3 = __expf(e.w);
                float s0 = eT[0]  * q0 + eT[1]  * q1 + eT[2]  * q2 + eT[3]  * q3;
                float s1 = eT[4]  * q0 + eT[5]  * q1 + eT[6]  * q2 + eT[7]  * q3;
                float s2 = eT[8]  * q0 + eT[9]  * q1 + eT[10] * q2 + eT[11] * q3;
                float s3 = eT[12] * q0 + eT[13] * q1 + eT[14] * q2 + eT[15] * q3;
                pr0 *= (m != 0.f) ? s0 : 1.0f;
                pr1 *= (m != 0.f) ? s1 : 1.0f;
                pr2 *= (m != 0.f) ? s2 : 1.0f;
                pr3 *= (m != 0.f) ? s3 : 1.0f;
            }
        }
        c0 += __logf(pr0);
        c1 += __logf(pr1);
        c2 += __logf(pr2);
        c3 += __logf(pr3);
    }

    // warp-wide sums of {c0,c1,c2,c3,gold}
    float v[5] = {c0, c1, c2, c3, gold};
    #pragma unroll
    for (int k = 0; k < 5; ++k) {
        float x = v[k];
        x += __shfl_xor_sync(full, x, 16);
        x += __shfl_xor_sync(full, x, 8);
        x += __shfl_xor_sync(full, x, 4);
        x += __shfl_xor_sync(full, x, 2);
        x += __shfl_xor_sync(full, x, 1);
        v[k] = x;
    }

    if (lane == 0) {
        const float f0 = a0 + v[0];
        const float f1 = a1 + v[1];
        const float f2 = a2 + v[2];
        const float f3 = a3 + v[3];
        const float mx = fmaxf(fmaxf(f0, f1), fmaxf(f2, f3));
        const float logZ = mx + __logf(__expf(f0 - mx) + __expf(f1 - mx) +
                                       __expf(f2 - mx) + __expf(f3 - mx));
        g_partial[b] = logZ - v[4];
    }

    // ---- threadfence-reduction: last block to finish sums everything ----
    __threadfence();
    __syncthreads();
    if (threadIdx.x == 0) {
        unsigned int old = atomicAdd(&g_ticket, 1u);
        // modulo keeps this correct across graph replays without a reset kernel
        // (2^32 is divisible by gridDim.x = 2048)
        s_is_last = ((old % gridDim.x) == gridDim.x - 1u);
    }
    __syncthreads();

    if (s_is_last) {
        double s = 0.0;
        for (int i = threadIdx.x; i < B; i += NTHREADS) s += (double)g_partial[i];
        shred[threadIdx.x] = s;
        __syncthreads();
        #pragma unroll
        for (int off = NTHREADS / 2; off > 0; off >>= 1) {
            if (threadIdx.x < off) shred[threadIdx.x] += shred[threadIdx.x + off];
            __syncthreads();
        }
        if (threadIdx.x == 0) out[0] = (float)(shred[0] / (double)B);
    }
}

extern "C" void kernel_launch(void* const* d_in, const int* in_sizes, int n_in,
                              void* d_out, int out_size)
{
    const float* emissions   = (const float*)d_in[0];
    const void*  tags        = (const void*)d_in[1];
    const void*  mask        = (const void*)d_in[2];
    const float* transitions = (const float*)d_in[3];

    const int B = in_sizes[0] / (T_LEN * 4);   // emissions: B*T*4 floats

    crf_warp_kernel<<<B / WARPS_PER_BLOCK, NTHREADS>>>(
        emissions, tags, mask, transitions, (float*)d_out, B);
}